// round 6
// baseline (speedup 1.0000x reference)
#include <cuda_runtime.h>
#include <cuda_bf16.h>

#define TOK    9216
#define NTOT   288
#define LAT    256
#define DIN    512
#define NE     8
#define HID    128
#define OUTD   16384
#define BMOFF  75497472
#define AUXOFF 150994944

typedef unsigned long long ull;

// ---------------- device scratch (no allocation allowed) ----------------
__device__ float g_Hg[2 * TOK * HID];        // gate-scaled silu hidden, per slot
__device__ int   g_list[2][NE][TOK];         // token lists per (slot, expert)
__device__ int   g_cnt[2][NE];
__device__ float g_tokG[2 * TOK];            // gate per (slot, token)
__device__ float g_psum[96][NE];             // per-(b,s) softmax prob partials
__device__ float g_lsum[96][NE];             // per-(b,s) load partials

__device__ __forceinline__ void fma2(ull& d, ull a, ull b) {
    asm("fma.rn.f32x2 %0, %1, %2, %0;" : "+l"(d) : "l"(a), "l"(b));
}
__device__ __forceinline__ ull pack2(float x) {
    ull r; asm("mov.b64 %0, {%1, %1};" : "=l"(r) : "f"(x)); return r;
}

// ---------------- K0: reset counters (device globals persist across graph replays)
__global__ void k_zero() {
    if (threadIdx.x < 16) ((int*)g_cnt)[threadIdx.x] = 0;
}

// ---------------- K1: routing. 96 blocks = one per (b, segment); 4 warps x 24 tokens.
__global__ void k_route(const float* __restrict__ z, const float* __restrict__ emb,
                        const float* __restrict__ Wr, const float* __restrict__ br) {
    int blk = blockIdx.x;            // b*3 + s
    int b = blk / 3, s = blk - b * 3;
    int warp = threadIdx.x >> 5, lane = threadIdx.x & 31;
    float accP = 0.f, accL = 0.f;    // lanes 0..7 accumulate for e == lane

    for (int it = 0; it < 24; it++) {
        int tt = warp * 24 + it;
        int n  = s * 96 + tt;
        int t  = b * NTOT + n;
        float lg[8];
#pragma unroll
        for (int e = 0; e < 8; e++) lg[e] = 0.f;
        const float* zr = z + (size_t)t * LAT;
        const float* er = emb + (size_t)n * LAT;
        for (int i = lane; i < DIN; i += 32) {
            float xv = (i < LAT) ? zr[i] : er[i - LAT];
            const float4 w0 = *(const float4*)(Wr + i * 8);
            const float4 w1 = *(const float4*)(Wr + i * 8 + 4);
            lg[0] += xv * w0.x; lg[1] += xv * w0.y; lg[2] += xv * w0.z; lg[3] += xv * w0.w;
            lg[4] += xv * w1.x; lg[5] += xv * w1.y; lg[6] += xv * w1.z; lg[7] += xv * w1.w;
        }
#pragma unroll
        for (int off = 16; off > 0; off >>= 1) {
#pragma unroll
            for (int e = 0; e < 8; e++) lg[e] += __shfl_xor_sync(0xffffffffu, lg[e], off);
        }
#pragma unroll
        for (int e = 0; e < 8; e++) lg[e] = (lg[e] + br[e]) * (1.0f / 1.5f);

        // top-2 (lowest index wins ties, matching jax top_k)
        int e0 = 0; float v0 = lg[0];
#pragma unroll
        for (int e = 1; e < 8; e++) if (lg[e] > v0) { v0 = lg[e]; e0 = e; }
        int e1 = -1; float v1 = -3.4e38f;
#pragma unroll
        for (int e = 0; e < 8; e++) if (e != e0 && lg[e] > v1) { v1 = lg[e]; e1 = e; }
        float ex = __expf(v1 - v0);
        float g0 = 1.f / (1.f + ex);
        float g1 = ex * g0;

        float den = 0.f, pr[8];
#pragma unroll
        for (int e = 0; e < 8; e++) { pr[e] = __expf(lg[e] - v0); den += pr[e]; }
        float rden = 1.f / den;
        if (lane < 8) {
            accP += pr[lane] * rden;
            accL += (lane == e0 ? g0 : 0.f) + (lane == e1 ? g1 : 0.f);
        }
        if (lane == 0) {
            g_tokG[t]       = g0;
            g_tokG[TOK + t] = g1;
            int p0 = atomicAdd(&g_cnt[0][e0], 1); g_list[0][e0][p0] = t;
            int p1 = atomicAdd(&g_cnt[1][e1], 1); g_list[1][e1][p1] = t;
        }
    }
    __shared__ float sP[4][8], sL[4][8];
    if (lane < 8) { sP[warp][lane] = accP; sL[warp][lane] = accL; }
    __syncthreads();
    if (threadIdx.x < 8) {
        float p = 0.f, l = 0.f;
        for (int w = 0; w < 4; w++) { p += sP[w][threadIdx.x]; l += sL[w][threadIdx.x]; }
        g_psum[blk][threadIdx.x] = p;
        g_lsum[blk][threadIdx.x] = l;
    }
}

// ---------------- K2: hidden GEMM per (slot, expert): [cnt,512] @ [512,128], silu, *gate
__global__ void __launch_bounds__(256) k_hidden(const float* __restrict__ z,
                                                const float* __restrict__ emb,
                                                const float* __restrict__ W1,
                                                const float* __restrict__ b1) {
    int slot = blockIdx.z, e = blockIdx.y;
    int cnt = g_cnt[slot][e];
    int m0 = blockIdx.x * 64;
    if (m0 >= cnt) return;
    int rows = min(64, cnt - m0);

    __shared__ __align__(16) float Xs[16][64];
    __shared__ __align__(16) float Ws[16][128];
    __shared__ int   stok[64];
    __shared__ float sg[64];

    int tid = threadIdx.x;
    if (tid < 64) {
        int t = (tid < rows) ? g_list[slot][e][m0 + tid] : -1;
        stok[tid] = t;
        sg[tid]   = (t >= 0) ? g_tokG[slot * TOK + t] : 0.f;
    }
    __syncthreads();

    int tx = tid & 15, ty = tid >> 4;
    int j0 = tx * 8, mr = ty * 4;
    float acc[4][8];
#pragma unroll
    for (int a = 0; a < 4; a++)
#pragma unroll
        for (int j = 0; j < 8; j++) acc[a][j] = 0.f;

    const float* W1e = W1 + (size_t)e * DIN * HID;
    int lm = tid >> 2, lq = (tid & 3) * 4;       // X-load mapping
    int lk = tid >> 4, ln = (tid & 15) * 8;      // W-load mapping

    for (int k0 = 0; k0 < DIN; k0 += 16) {
        float4 v = make_float4(0.f, 0.f, 0.f, 0.f);
        int t = stok[lm];
        if (t >= 0) {
            int kk = k0 + lq;
            if (kk < LAT) v = *(const float4*)(z + (size_t)t * LAT + kk);
            else          v = *(const float4*)(emb + (size_t)(t % NTOT) * LAT + (kk - LAT));
        }
        const float* src = W1e + (size_t)(k0 + lk) * HID + ln;
        float4 w0 = *(const float4*)src;
        float4 w1 = *(const float4*)(src + 4);

        __syncthreads();    // previous compute done before overwrite
        Xs[lq + 0][lm] = v.x; Xs[lq + 1][lm] = v.y; Xs[lq + 2][lm] = v.z; Xs[lq + 3][lm] = v.w;
        *(float4*)&Ws[lk][ln]     = w0;
        *(float4*)&Ws[lk][ln + 4] = w1;
        __syncthreads();

#pragma unroll
        for (int kk = 0; kk < 16; kk++) {
            float4 a  = *(const float4*)&Xs[kk][mr];
            float4 b0 = *(const float4*)&Ws[kk][j0];
            float4 b1v = *(const float4*)&Ws[kk][j0 + 4];
            float av[4] = {a.x, a.y, a.z, a.w};
            float bv[8] = {b0.x, b0.y, b0.z, b0.w, b1v.x, b1v.y, b1v.z, b1v.w};
#pragma unroll
            for (int mm = 0; mm < 4; mm++)
#pragma unroll
                for (int jj = 0; jj < 8; jj++)
                    acc[mm][jj] = fmaf(av[mm], bv[jj], acc[mm][jj]);
        }
    }

    const float* b1e = b1 + e * HID;
#pragma unroll
    for (int mm = 0; mm < 4; mm++) {
        int m = mr + mm;
        int t = stok[m];
        if (t < 0) continue;
        float g = sg[m];
        float o[8];
#pragma unroll
        for (int jj = 0; jj < 8; jj++) {
            float c = acc[mm][jj] + b1e[j0 + jj];
            float sv = 1.f / (1.f + __expf(-c));   // silu = c * sigmoid(c)
            o[jj] = c * sv * g;
        }
        float* dst = g_Hg + ((size_t)(slot * TOK + t)) * HID + j0;
        *(float4*)dst       = make_float4(o[0], o[1], o[2], o[3]);
        *(float4*)(dst + 4) = make_float4(o[4], o[5], o[6], o[7]);
    }
}

// ---------------- K3: output GEMM per (slot, expert). Tile 64 tokens x 128 cols,
// col j -> o(j) = (j>>3)*1024 + h0 + (j&7)  (all 16 r x 8 h) so Bm rows write coalesced.
__global__ void __launch_bounds__(128) k_out(const float* __restrict__ W2,
                                             const float* __restrict__ b2,
                                             float* __restrict__ out, int slot) {
    int e = blockIdx.z;
    int cnt = g_cnt[slot][e];
    int m0 = blockIdx.x * 64;
    if (m0 >= cnt) return;
    int rows = min(64, cnt - m0);
    int h0 = blockIdx.y * 8;

    __shared__ __align__(16) float As[128 * 64];   // [k][m]; reused as C tile [m][128]
    __shared__ __align__(16) float Bs[2][8 * 128];
    __shared__ int   sbase[64];
    __shared__ float sg[64];

    int tid = threadIdx.x;
    if (tid < 64) {
        int base = -1; float g = 0.f;
        if (tid < rows) {
            int t = g_list[slot][e][m0 + tid];
            g = g_tokG[slot * TOK + t];
            int b = t / NTOT, n = t - b * NTOT;
            int s = n / 96, rem = n - s * 96, l = rem >> 2, jt = rem & 3;
            int chunk = ((b * 3 + s) * 24 + l) * 2 + (jt >> 1);
            base = chunk * OUTD + (jt & 1);        // low bit = isBm (base multiple of 16384)
        }
        sbase[tid] = base; sg[tid] = g;
    }
    // load As (K-major): 2 threads per token row
    {
        int m = tid >> 1, half = tid & 1;
        int t = (m < rows) ? g_list[slot][e][m0 + m] : -1;
        const float* src = (t >= 0) ? (g_Hg + ((size_t)(slot * TOK + t)) * HID + half * 64)
                                    : (const float*)0;
#pragma unroll
        for (int q = 0; q < 16; q++) {
            float4 v = make_float4(0.f, 0.f, 0.f, 0.f);
            if (t >= 0) v = *(const float4*)(src + q * 4);
            int k = half * 64 + q * 4;
            As[(k + 0) * 64 + m] = v.x; As[(k + 1) * 64 + m] = v.y;
            As[(k + 2) * 64 + m] = v.z; As[(k + 3) * 64 + m] = v.w;
        }
    }
    const float* W2e = W2 + (size_t)e * HID * OUTD;
    int lk = tid >> 4, lr = tid & 15;
    const float* bsrc0 = W2e + (size_t)lk * OUTD + lr * 1024 + h0;

    float4 p0 = *(const float4*)bsrc0;
    float4 p1 = *(const float4*)(bsrc0 + 4);
    {
        float* d = &Bs[0][lk * 128 + lr * 8];
        *(float4*)d = p0; *(float4*)(d + 4) = p1;
    }
    __syncthreads();

    int tx = tid & 15, ty = tid >> 4;
    int j0 = tx * 8, mr = ty * 8;
    ull acc[8][4];
#pragma unroll
    for (int a = 0; a < 8; a++)
#pragma unroll
        for (int p = 0; p < 4; p++) acc[a][p] = 0ull;

    for (int c = 0; c < 16; c++) {
        if (c < 15) {
            const float* bs = bsrc0 + (size_t)(c + 1) * 8 * OUTD;
            p0 = *(const float4*)bs;
            p1 = *(const float4*)(bs + 4);
        }
        const float* Bp = &Bs[c & 1][0];
#pragma unroll
        for (int kk = 0; kk < 8; kk++) {
            const float* ar = &As[(c * 8 + kk) * 64 + mr];
            float4 a0 = *(const float4*)ar;
            float4 a1 = *(const float4*)(ar + 4);
            ull A2[8];
            A2[0] = pack2(a0.x); A2[1] = pack2(a0.y); A2[2] = pack2(a0.z); A2[3] = pack2(a0.w);
            A2[4] = pack2(a1.x); A2[5] = pack2(a1.y); A2[6] = pack2(a1.z); A2[7] = pack2(a1.w);
            ulonglong2 b01 = *(const ulonglong2*)(Bp + kk * 128 + j0);
            ulonglong2 b23 = *(const ulonglong2*)(Bp + kk * 128 + j0 + 4);
            ull B2[4] = {b01.x, b01.y, b23.x, b23.y};
#pragma unroll
            for (int mm = 0; mm < 8; mm++)
#pragma unroll
                for (int p = 0; p < 4; p++)
                    fma2(acc[mm][p], A2[mm], B2[p]);
        }
        if (c < 15) {
            float* d = &Bs[(c + 1) & 1][lk * 128 + lr * 8];
            *(float4*)d = p0; *(float4*)(d + 4) = p1;
        }
        __syncthreads();
    }

    // stage C tile through smem so each row can use its own (A vs Bm) thread mapping
    float* Cs = As;
#pragma unroll
    for (int mm = 0; mm < 8; mm++)
#pragma unroll
        for (int p = 0; p < 4; p++)
            *(ull*)&Cs[(mr + mm) * 128 + j0 + p * 2] = acc[mm][p];
    __syncthreads();

    const float* b2e = b2 + e * OUTD;
    float bA = b2e[(tid >> 3) * 1024 + h0 + (tid & 7)];
    float bB = b2e[(tid & 15) * 1024 + h0 + (tid >> 4)];
    int jB = (tid & 15) * 8 + (tid >> 4);
    int aoffA = (tid >> 3) * 1024 + h0 + (tid & 7);
    int aoffB = h0 * 16 + tid;

#pragma unroll 4
    for (int m = 0; m < 64; m++) {
        int bs = sbase[m];
        if (bs < 0) continue;
        float g = sg[m];
        size_t addr; float v;
        if (bs & 1) {   // Bm row: contiguous 128-float write
            v = Cs[m * 128 + jB] + g * bB;
            addr = (size_t)BMOFF + (size_t)(bs & ~1) + aoffB;
        } else {        // A row: 32B-sector writes
            v = Cs[m * 128 + tid] + g * bA;
            addr = (size_t)bs + aoffA;
        }
        if (slot == 0) out[addr] = v;
        else           out[addr] += v;
    }
}

// ---------------- K4: aux loss (deterministic serial reduce of partials)
__global__ void k_aux(float* __restrict__ out) {
    if (threadIdx.x == 0 && blockIdx.x == 0) {
        double aux = 0.0;
        for (int s = 0; s < 3; s++) {
            double dot = 0.0;
            for (int e = 0; e < NE; e++) {
                double P = 0.0, L = 0.0;
                for (int b = 0; b < 32; b++) {
                    P += (double)g_psum[b * 3 + s][e];
                    L += (double)g_lsum[b * 3 + s][e];
                }
                dot += P * L;
            }
            double a = 8.0 * dot / (3072.0 * 3072.0) - 1.0;
            if (a > 0.0) aux += a;
        }
        out[AUXOFF] = (float)aux;
    }
}

extern "C" void kernel_launch(void* const* d_in, const int* in_sizes, int n_in,
                              void* d_out, int out_size) {
    const float* z   = (const float*)d_in[0];
    const float* emb = (const float*)d_in[1];
    const float* Wr  = (const float*)d_in[2];
    const float* br  = (const float*)d_in[3];
    const float* W1  = (const float*)d_in[4];
    const float* b1  = (const float*)d_in[5];
    const float* W2  = (const float*)d_in[6];
    const float* b2  = (const float*)d_in[7];
    float* out = (float*)d_out;
    (void)in_sizes; (void)n_in; (void)out_size;

    k_zero<<<1, 32>>>();
    k_route<<<96, 128>>>(z, emb, Wr, br);
    k_hidden<<<dim3(TOK / 64, NE, 2), 256>>>(z, emb, W1, b1);
    k_out<<<dim3(TOK / 64, OUTD / 128, NE), 128>>>(W2, b2, out, 0);
    k_out<<<dim3(TOK / 64, OUTD / 128, NE), 128>>>(W2, b2, out, 1);
    k_aux<<<1, 32>>>(out);
}